// round 6
// baseline (speedup 1.0000x reference)
#include <cuda_runtime.h>
#include <cuda_bf16.h>
#include <stdint.h>

// Problem constants
#define BB   64
#define LMAX 4096
#define DD   128
#define RL   64
#define RD   16
#define DOUT 512
#define LN_EPS 1e-5f

#define CHUNK 512   // L-rows per stage-A block
#define TILE  64    // L-rows per inner tile

typedef unsigned long long u64;

// -------- device scratch (no allocations allowed) --------
__device__ int      g_mode;            // 0=i32, 1=u8, 2=f32, 3=bf16
__device__ int      g_len[BB];
__device__ unsigned g_bar[4];
__device__ float    g_U[BB * RL * RD];     // 64*1024
__device__ float    g_z[BB * DOUT];
__device__ float    g_h[BB * DOUT];
__device__ float    g_ha[BB * DOUT];

// ---------------- f32x2 packed-FMA helpers ----------------
__device__ __forceinline__ u64 pack2(float x) {
    u64 r; asm("mov.b64 %0, {%1, %1};" : "=l"(r) : "f"(x)); return r;
}
__device__ __forceinline__ void fma2(u64& d, u64 a, u64 b) {
    asm("fma.rn.f32x2 %0, %1, %2, %0;" : "+l"(d) : "l"(a), "l"(b));
}
__device__ __forceinline__ float2 unpack2(u64 v) {
    float2 r; asm("mov.b64 {%0, %1}, %2;" : "=f"(r.x), "=f"(r.y) : "l"(v)); return r;
}

// ---------------- cp.async helpers ----------------
__device__ __forceinline__ void cp_async16(float* smem_dst, const float* gsrc, int src_bytes) {
    unsigned sa = (unsigned)__cvta_generic_to_shared(smem_dst);
    asm volatile("cp.async.cg.shared.global [%0], [%1], 16, %2;\n"
                 :: "r"(sa), "l"(gsrc), "r"(src_bytes));
}
__device__ __forceinline__ void cp_commit() {
    asm volatile("cp.async.commit_group;\n");
}
template<int N> __device__ __forceinline__ void cp_wait() {
    asm volatile("cp.async.wait_group %0;\n" :: "n"(N));
}

// -------------------------------------------------------------------
// k0: block 0 detects mask dtype; blocks 1..7 zero all scratch + out.
// mask[0][0] is always true (lengths >= 1).
// -------------------------------------------------------------------
__global__ void k_detect(const unsigned char* __restrict__ mask_raw,
                         float* __restrict__ out) {
    int t = threadIdx.x;
    if (blockIdx.x == 0) {
        __shared__ int s_flag;
        const unsigned* mw = (const unsigned*)mask_raw;
        unsigned W0 = mw[0];
        if (W0 == 0x3F800000u) { if (t == 0) g_mode = 2; return; }
        if (W0 == 0x3F803F80u || W0 == 0x00003F80u) { if (t == 0) g_mode = 3; return; }
        if (t == 0) s_flag = 0;
        __syncthreads();
        int local = 0;
        #pragma unroll 4
        for (int i = t; i < 16384; i += 512) {   // first 64 KB only (in-bounds all dtypes)
            unsigned w = mw[i];
            if (w & 0xFFFFFF00u) local = 1;      // byte 1..3 nonzero -> u8
        }
        if (local) atomicOr(&s_flag, 1);
        __syncthreads();
        if (t == 0) g_mode = s_flag ? 1 : 0;
    } else {
        int zb = blockIdx.x - 1;                 // 0..6
        // zero g_U | g_z | g_h | out  (163840 floats)
        for (int i = zb * 512 + t; i < 163840; i += 7 * 512) {
            if (i < 65536)              g_U[i] = 0.0f;
            else if (i < 98304)         g_z[i - 65536] = 0.0f;
            else if (i < 131072)        g_h[i - 98304] = 0.0f;
            else                        out[i - 131072] = 0.0f;
        }
        if (zb == 0) {
            if (t < BB) g_len[t] = 0;
            if (t >= 64 && t < 68) g_bar[t - 64] = 0u;
        }
    }
}

// -------------------------------------------------------------------
// k1: lengths. grid 128: 2 blocks per batch row, atomicAdd partials.
// -------------------------------------------------------------------
__global__ void k_prep(const unsigned char* __restrict__ mask_raw) {
    int b    = blockIdx.x >> 1;
    int half = blockIdx.x & 1;
    int t    = threadIdx.x;
    int mode = g_mode;
    int base = b * LMAX + half * (LMAX / 2);
    int cnt = 0;
    if (mode == 0) {
        const int* m = (const int*)mask_raw;
        for (int i = t; i < LMAX / 2; i += 256) cnt += (m[base + i] != 0);
    } else if (mode == 1) {
        const unsigned char* m = mask_raw;
        for (int i = t; i < LMAX / 2; i += 256) cnt += (m[base + i] != 0);
    } else if (mode == 2) {
        const float* m = (const float*)mask_raw;
        for (int i = t; i < LMAX / 2; i += 256) cnt += (m[base + i] != 0.0f);
    } else {
        const unsigned short* m = (const unsigned short*)mask_raw;
        for (int i = t; i < LMAX / 2; i += 256) cnt += (m[base + i] != 0);
    }
    for (int o = 16; o > 0; o >>= 1) cnt += __shfl_down_sync(0xFFFFFFFFu, cnt, o);
    __shared__ int sred[8];
    if ((t & 31) == 0) sred[t >> 5] = cnt;
    __syncthreads();
    if (t == 0) {
        int tot = 0;
        #pragma unroll
        for (int i = 0; i < 8; ++i) tot += sred[i];
        atomicAdd(&g_len[b], tot);
    }
}

// -------------------------------------------------------------------
// k2 (heavy): per (b, 512-row chunk), TILE=64, f32x2 packed FMA.
// smem (floats): Bs[2048] | Ys[64*20] | Xs[64*132] | As0[4096] | As1[4096]
// -------------------------------------------------------------------
__device__ __forceinline__ void issue_tile64(const float* embB, const float* Ac,
        float* Xbuf, float* Abuf, int lt, int valid, int t) {
    #pragma unroll
    for (int j = 0; j < 8; ++j) {             // 2048 X float4-chunks
        int i = t + j * 256;
        int row = i >> 5, seg = i & 31;
        cp_async16(Xbuf + row * 132 + seg * 4,
                   embB + (size_t)(lt + row) * DD + seg * 4,
                   (row < valid) ? 16 : 0);
    }
    #pragma unroll
    for (int j = 0; j < 4; ++j) {             // 1024 A float4-chunks
        int i = t + j * 256;
        int row = i >> 4, seg = i & 15;
        cp_async16(Abuf + row * RL + seg * 4,
                   Ac + (size_t)(lt + row) * RL + seg * 4, 16);
    }
}

__global__ __launch_bounds__(256) void k_stageA(
        const float* __restrict__ emb,
        const float* __restrict__ Bc,
        const float* __restrict__ Ac) {
    extern __shared__ float sm[];
    float* Bs  = sm;             // 2048
    float* Ys  = sm + 2048;      // 1280 (64 rows * stride 20)
    float* Xs  = sm + 3328;      // 8448 (64 rows * stride 132)
    float* As0 = sm + 11776;     // 4096
    float* As1 = sm + 15872;     // 4096

    int b     = blockIdx.x & (BB - 1);
    int chunk = blockIdx.x >> 6;
    int len   = g_len[b];
    int l0    = chunk * CHUNK;
    if (l0 >= len) return;
    int nrows = min(CHUNK, len - l0);
    int ntiles = (nrows + TILE - 1) >> 6;

    int t = threadIdx.x;
    const float* embB = emb + (size_t)b * LMAX * DD;

    issue_tile64(embB, Ac, Xs, As0, l0, min(TILE, nrows), t);
    cp_commit();
    #pragma unroll
    for (int j = 0; j < 2; ++j) {
        int i = t + j * 256;
        *(float4*)(Bs + i * 4) = *(const float4*)(Bc + i * 4);
    }

    // GEMM1 mapping: warp w: cg=w&3 (cols 4cg..4cg+3), row=(w>>2)*32+lane
    int w    = t >> 5;
    int lane = t & 31;
    int cg   = w & 3;
    int row  = ((w >> 2) << 5) + lane;
    const float* xrow = Xs + row * 132;
    const float* bcol = Bs + cg * 4;
    float* yout = Ys + row * 20 + cg * 4;

    // GEMM2 mapping (accumulators persist): k=t&63, rg=t>>6
    int k_own = t & 63;
    int rg    = t >> 6;
    u64 acc01 = 0ull, acc23 = 0ull;
    const float* yin = Ys + rg * 4;

    for (int tile = 0; tile < ntiles; ++tile) {
        const float* Ab = (tile & 1) ? As1 : As0;
        cp_wait<0>();
        __syncthreads();

        // ---- GEMM1 (f32x2): y[row][4cg..] = sum_d X[row][d]*B[d][4cg..] ----
        u64 y01 = 0ull, y23 = 0ull;
        #pragma unroll 8
        for (int s = 0; s < 32; ++s) {
            float4 x4 = *(const float4*)(xrow + s * 4);
            const float* bbase = bcol + (4 * s) * RD;
            ulonglong2 b0 = *(const ulonglong2*)(bbase);
            ulonglong2 b1 = *(const ulonglong2*)(bbase + RD);
            ulonglong2 b2 = *(const ulonglong2*)(bbase + 2 * RD);
            ulonglong2 b3 = *(const ulonglong2*)(bbase + 3 * RD);
            u64 xx;
            xx = pack2(x4.x); fma2(y01, xx, b0.x); fma2(y23, xx, b0.y);
            xx = pack2(x4.y); fma2(y01, xx, b1.x); fma2(y23, xx, b1.y);
            xx = pack2(x4.z); fma2(y01, xx, b2.x); fma2(y23, xx, b2.y);
            xx = pack2(x4.w); fma2(y01, xx, b3.x); fma2(y23, xx, b3.y);
        }
        {
            float2 lo = unpack2(y01), hi = unpack2(y23);
            *(float4*)yout = make_float4(lo.x, lo.y, hi.x, hi.y);
        }
        __syncthreads();              // Ys complete; X now dead

        if (tile + 1 < ntiles) {
            int lt    = l0 + (tile + 1) * TILE;
            int valid = min(TILE, nrows - (tile + 1) * TILE);
            issue_tile64(embB, Ac, Xs, (tile & 1) ? As0 : As1, lt, valid, t);
            cp_commit();
        }

        // ---- GEMM2 (f32x2): U[k][4rg..] += sum_l A[l][k]*y[l][4rg..] ----
        #pragma unroll 8
        for (int l = 0; l < TILE; ++l) {
            u64 aa = pack2(Ab[l * RL + k_own]);
            ulonglong2 y2 = *(const ulonglong2*)(yin + l * 20);
            fma2(acc01, aa, y2.x);
            fma2(acc23, aa, y2.y);
        }
    }

    float2 a01 = unpack2(acc01), a23 = unpack2(acc23);
    float* Ub = g_U + b * (RL * RD) + k_own * RD + rg * 4;
    atomicAdd(Ub + 0, a01.x);
    atomicAdd(Ub + 1, a01.y);
    atomicAdd(Ub + 2, a23.x);
    atomicAdd(Ub + 3, a23.y);
}

// -------------------------------------------------------------------
// Fused tail: one kernel, grid 128 (co-resident), spin grid-barriers.
//   P0: z = U @ Hc          (16 coltiles x 8 ksplit = 128 blocks)
//   P1: h = z @ W1          (16 coltiles x 4 ksplit =  64 blocks)
//   P2: LN(h)+ReLU -> ha    (64 blocks, 1 row each)
//   P3: out = ha @ W2 + b2  (64 blocks)
// -------------------------------------------------------------------
__device__ __forceinline__ void grid_bar(int idx) {
    __syncthreads();
    if (threadIdx.x == 0) {
        __threadfence();
        atomicAdd(&g_bar[idx], 1u);
        volatile unsigned* p = &g_bar[idx];
        while (*p < 128u) { }
    }
    __syncthreads();
}

__device__ __forceinline__ void tail_gemm_phase(
        const float* __restrict__ A, const float* __restrict__ W,
        float* __restrict__ C, const float* __restrict__ bias,
        int Ktot, int nt, int ks, float* As, float* Ws, int t) {
    const int SA = 129;                       // KC = 128
    int n0 = nt * 32, kbase = ks * 128;
    #pragma unroll 4
    for (int i = t; i < BB * 128; i += 256) {
        int row = i >> 7, k = i & 127;
        As[row * SA + k] = A[(size_t)row * Ktot + kbase + k];
    }
    #pragma unroll 4
    for (int i = t; i < 128 * 8; i += 256) {
        int row = i >> 3, seg = i & 7;
        *(float4*)&Ws[row * 32 + seg * 4] =
            *(const float4*)&W[(size_t)(kbase + row) * DOUT + n0 + seg * 4];
    }
    __syncthreads();

    int l = t & 31, wn = t >> 5;
    u64 c0a = 0ull, c0b = 0ull, c1a = 0ull, c1b = 0ull;
    const float* a0p = As + l * SA;
    const float* a1p = As + (l + 32) * SA;
    const float* wp  = Ws + wn * 4;
    #pragma unroll 8
    for (int k = 0; k < 128; ++k) {
        u64 aa0 = pack2(a0p[k]);
        u64 aa1 = pack2(a1p[k]);
        ulonglong2 w2 = *(const ulonglong2*)(wp + k * 32);
        fma2(c0a, aa0, w2.x); fma2(c0b, aa0, w2.y);
        fma2(c1a, aa1, w2.x); fma2(c1b, aa1, w2.y);
    }
    int col = n0 + wn * 4;
    float2 r0a = unpack2(c0a), r0b = unpack2(c0b);
    float2 r1a = unpack2(c1a), r1b = unpack2(c1b);
    if (bias != nullptr && ks == 0) {
        float4 bv = *(const float4*)(bias + col);
        r0a.x += bv.x; r0a.y += bv.y; r0b.x += bv.z; r0b.y += bv.w;
        r1a.x += bv.x; r1a.y += bv.y; r1b.x += bv.z; r1b.y += bv.w;
    }
    float* Cp0 = C + (size_t)l * DOUT + col;
    float* Cp1 = C + (size_t)(l + 32) * DOUT + col;
    atomicAdd(Cp0 + 0, r0a.x); atomicAdd(Cp0 + 1, r0a.y);
    atomicAdd(Cp0 + 2, r0b.x); atomicAdd(Cp0 + 3, r0b.y);
    atomicAdd(Cp1 + 0, r1a.x); atomicAdd(Cp1 + 1, r1a.y);
    atomicAdd(Cp1 + 2, r1b.x); atomicAdd(Cp1 + 3, r1b.y);
}

__global__ __launch_bounds__(256) void k_tail(
        const float* __restrict__ Hc, const float* __restrict__ W1,
        const float* __restrict__ W2, const float* __restrict__ b1,
        const float* __restrict__ lnw, const float* __restrict__ lnb,
        const float* __restrict__ b2, float* __restrict__ out) {
    extern __shared__ float fsm[];
    float* As = fsm;                 // 64*129 = 8256
    float* Ws = fsm + BB * 129;      // 128*32 = 4096  (total 49408 B)
    int bid = blockIdx.x, t = threadIdx.x;

    // P0: z = U @ Hc  (Ktot=1024, 8 ksplits)
    tail_gemm_phase(g_U, Hc, g_z, nullptr, 1024, bid & 15, bid >> 4, As, Ws, t);
    grid_bar(0);

    // P1: h = z @ W1  (Ktot=512, 4 ksplits, blocks 0..63)
    if (bid < 64)
        tail_gemm_phase(g_z, W1, g_h, nullptr, 512, bid & 15, bid >> 4, As, Ws, t);
    grid_bar(1);

    // P2: LayerNorm + ReLU on row bid (blocks 0..63)
    if (bid < 64) {
        float v0 = g_h[bid * DOUT + t]       + b1[t];
        float v1 = g_h[bid * DOUT + 256 + t] + b1[256 + t];
        float s  = v0 + v1;
        float sq = v0 * v0 + v1 * v1;
        for (int o = 16; o > 0; o >>= 1) {
            s  += __shfl_down_sync(0xFFFFFFFFu, s,  o);
            sq += __shfl_down_sync(0xFFFFFFFFu, sq, o);
        }
        __shared__ float rs[8], rq[8];
        if ((t & 31) == 0) { rs[t >> 5] = s; rq[t >> 5] = sq; }
        __syncthreads();
        float tot = 0.f, totq = 0.f;
        #pragma unroll
        for (int i = 0; i < 8; ++i) { tot += rs[i]; totq += rq[i]; }
        float mu   = tot / (float)DOUT;
        float var  = fmaxf(totq / (float)DOUT - mu * mu, 0.f);
        float rstd = rsqrtf(var + LN_EPS);
        float o0 = (v0 - mu) * rstd * lnw[t]       + lnb[t];
        float o1 = (v1 - mu) * rstd * lnw[256 + t] + lnb[256 + t];
        g_ha[bid * DOUT + t]       = fmaxf(o0, 0.f);
        g_ha[bid * DOUT + 256 + t] = fmaxf(o1, 0.f);
    }
    grid_bar(2);

    // P3: out = ha @ W2 + b2  (blocks 0..63)
    if (bid < 64)
        tail_gemm_phase(g_ha, W2, out, b2, 512, bid & 15, bid >> 4, As, Ws, t);
}

// -------------------------------------------------------------------
extern "C" void kernel_launch(void* const* d_in, const int* in_sizes, int n_in,
                              void* d_out, int out_size) {
    const float*         emb  = (const float*)d_in[0];
    const unsigned char* mask = (const unsigned char*)d_in[1];
    const float*         Bc   = (const float*)d_in[2];
    const float*         Ac   = (const float*)d_in[3];
    const float*         Hc   = (const float*)d_in[4];
    const float*         W1   = (const float*)d_in[5];
    const float*         b1   = (const float*)d_in[6];
    const float*         lnw  = (const float*)d_in[7];
    const float*         lnb  = (const float*)d_in[8];
    const float*         W2   = (const float*)d_in[9];
    const float*         b2   = (const float*)d_in[10];
    float* out = (float*)d_out;

    const int TAIL_SMEM = (BB * 129 + 128 * 32) * 4;   // 49408 B

    cudaFuncSetAttribute(k_stageA, cudaFuncAttributeMaxDynamicSharedMemorySize, 81920);
    cudaFuncSetAttribute(k_tail,   cudaFuncAttributeMaxDynamicSharedMemorySize, TAIL_SMEM);

    k_detect<<<8, 512>>>(mask, out);
    k_prep<<<128, 256>>>(mask);
    k_stageA<<<BB * (LMAX / CHUNK), 256, 79872>>>(emb, Bc, Ac);   // 512 blocks
    k_tail<<<128, 256, TAIL_SMEM>>>(Hc, W1, W2, b1, lnw, lnb, b2, out);
}

// round 8
// speedup vs baseline: 1.2451x; 1.2451x over previous
#include <cuda_runtime.h>
#include <cuda_bf16.h>
#include <stdint.h>

// Problem constants
#define BB   64
#define LMAX 4096
#define DD   128
#define RL   64
#define RD   16
#define DOUT 512
#define LN_EPS 1e-5f

#define CHUNK 512   // L-rows per stage-A block
#define TILE  64    // L-rows per inner tile

typedef unsigned long long u64;

// -------- device scratch (no allocations allowed) --------
__device__ int      g_mode;            // 0=i32, 1=u8, 2=f32, 3=bf16
__device__ float    g_U[BB * RL * RD];     // 64*1024
__device__ float    g_z[BB * DOUT];
__device__ float    g_h[BB * DOUT];
__device__ float    g_ha[BB * DOUT];

// ---------------- f32x2 packed-FMA helpers ----------------
__device__ __forceinline__ u64 pack2(float x) {
    u64 r; asm("mov.b64 %0, {%1, %1};" : "=l"(r) : "f"(x)); return r;
}
__device__ __forceinline__ void fma2(u64& d, u64 a, u64 b) {
    asm("fma.rn.f32x2 %0, %1, %2, %0;" : "+l"(d) : "l"(a), "l"(b));
}
__device__ __forceinline__ float2 unpack2(u64 v) {
    float2 r; asm("mov.b64 {%0, %1}, %2;" : "=f"(r.x), "=f"(r.y) : "l"(v)); return r;
}

// ---------------- cp.async helpers ----------------
__device__ __forceinline__ void cp_async16(float* smem_dst, const float* gsrc, int src_bytes) {
    unsigned sa = (unsigned)__cvta_generic_to_shared(smem_dst);
    asm volatile("cp.async.cg.shared.global [%0], [%1], 16, %2;\n"
                 :: "r"(sa), "l"(gsrc), "r"(src_bytes));
}
__device__ __forceinline__ void cp_commit() {
    asm volatile("cp.async.commit_group;\n");
}
template<int N> __device__ __forceinline__ void cp_wait() {
    asm volatile("cp.async.wait_group %0;\n" :: "n"(N));
}

// -------------------------------------------------------------------
// k0: block 0 detects mask dtype; blocks 1..7 zero all scratch + out.
// mask[0][0] is always true (lengths >= 1).
// -------------------------------------------------------------------
__global__ void k_detect(const unsigned char* __restrict__ mask_raw,
                         float* __restrict__ out) {
    int t = threadIdx.x;
    if (blockIdx.x == 0) {
        __shared__ int s_flag;
        const unsigned* mw = (const unsigned*)mask_raw;
        unsigned W0 = mw[0];
        if (W0 == 0x3F800000u) { if (t == 0) g_mode = 2; return; }
        if (W0 == 0x3F803F80u || W0 == 0x00003F80u) { if (t == 0) g_mode = 3; return; }
        if (t == 0) s_flag = 0;
        __syncthreads();
        int local = 0;
        #pragma unroll 4
        for (int i = t; i < 16384; i += 512) {   // first 64 KB only (in-bounds all dtypes)
            unsigned w = mw[i];
            if (w & 0xFFFFFF00u) local = 1;      // byte 1..3 nonzero -> u8
        }
        if (local) atomicOr(&s_flag, 1);
        __syncthreads();
        if (t == 0) g_mode = s_flag ? 1 : 0;
    } else {
        int zb = blockIdx.x - 1;                 // 0..6
        // zero g_U | g_z | g_h | out  (163840 floats)
        for (int i = zb * 512 + t; i < 163840; i += 7 * 512) {
            if (i < 65536)              g_U[i] = 0.0f;
            else if (i < 98304)         g_z[i - 65536] = 0.0f;
            else if (i < 131072)        g_h[i - 98304] = 0.0f;
            else                        out[i - 131072] = 0.0f;
        }
    }
}

// -------------------------------------------------------------------
// k2 (heavy): per (b, 512-row chunk), TILE=64, f32x2 packed FMA.
// Block computes its own valid-row count from its mask window
// (mask is contiguous-from-0, so window count == rows valid here).
// smem (floats): Bs[2048] | Ys[64*20] | Xs[64*132] | As0[4096] | As1[4096]
// -------------------------------------------------------------------
__device__ __forceinline__ void issue_tile64(const float* embB, const float* Ac,
        float* Xbuf, float* Abuf, int lt, int valid, int t) {
    #pragma unroll
    for (int j = 0; j < 8; ++j) {             // 2048 X float4-chunks
        int i = t + j * 256;
        int row = i >> 5, seg = i & 31;
        cp_async16(Xbuf + row * 132 + seg * 4,
                   embB + (size_t)(lt + row) * DD + seg * 4,
                   (row < valid) ? 16 : 0);
    }
    #pragma unroll
    for (int j = 0; j < 4; ++j) {             // 1024 A float4-chunks
        int i = t + j * 256;
        int row = i >> 4, seg = i & 15;
        cp_async16(Abuf + row * RL + seg * 4,
                   Ac + (size_t)(lt + row) * RL + seg * 4, 16);
    }
}

__global__ __launch_bounds__(256) void k_stageA(
        const float* __restrict__ emb,
        const float* __restrict__ Bc,
        const float* __restrict__ Ac,
        const unsigned char* __restrict__ mask_raw) {
    extern __shared__ float sm[];
    float* Bs  = sm;             // 2048
    float* Ys  = sm + 2048;      // 1280 (64 rows * stride 20)
    float* Xs  = sm + 3328;      // 8448 (64 rows * stride 132)
    float* As0 = sm + 11776;     // 4096
    float* As1 = sm + 15872;     // 4096

    int b     = blockIdx.x & (BB - 1);
    int chunk = blockIdx.x >> 6;
    int l0    = chunk * CHUNK;
    int t = threadIdx.x;

    // ---- count valid rows in this block's mask window ----
    {
        int mode = g_mode;
        int base = b * LMAX + l0;
        int cnt = 0;
        if (mode == 0) {
            const int* m = (const int*)mask_raw;
            cnt  = (m[base + t] != 0);
            cnt += (m[base + t + 256] != 0);
        } else if (mode == 1) {
            const unsigned char* m = mask_raw;
            cnt  = (m[base + t] != 0);
            cnt += (m[base + t + 256] != 0);
        } else if (mode == 2) {
            const float* m = (const float*)mask_raw;
            cnt  = (m[base + t] != 0.0f);
            cnt += (m[base + t + 256] != 0.0f);
        } else {
            const unsigned short* m = (const unsigned short*)mask_raw;
            cnt  = (m[base + t] != 0);
            cnt += (m[base + t + 256] != 0);
        }
        for (int o = 16; o > 0; o >>= 1) cnt += __shfl_down_sync(0xFFFFFFFFu, cnt, o);
        __shared__ int sred[8];
        __shared__ int s_nrows;
        if ((t & 31) == 0) sred[t >> 5] = cnt;
        __syncthreads();
        if (t == 0) {
            int tot = 0;
            #pragma unroll
            for (int i = 0; i < 8; ++i) tot += sred[i];
            s_nrows = tot;
        }
        __syncthreads();
        int nr = s_nrows;
        if (nr == 0) return;
        // stash in Bs[0] slot temporarily? no — just recompute below
        sred[0] = nr;           // reuse; all threads re-read after sync
        __syncthreads();
        // fallthrough with nrows in register
        #define NROWS_REG sred[0]
        int nrows = NROWS_REG;
        int ntiles = (nrows + TILE - 1) >> 6;

        const float* embB = emb + (size_t)b * LMAX * DD;

        issue_tile64(embB, Ac, Xs, As0, l0, min(TILE, nrows), t);
        cp_commit();
        #pragma unroll
        for (int j = 0; j < 2; ++j) {
            int i = t + j * 256;
            *(float4*)(Bs + i * 4) = *(const float4*)(Bc + i * 4);
        }

        // GEMM1 mapping: warp w: cg=w&3 (cols 4cg..4cg+3), row=(w>>2)*32+lane
        int w    = t >> 5;
        int lane = t & 31;
        int cg   = w & 3;
        int row  = ((w >> 2) << 5) + lane;
        const float* xrow = Xs + row * 132;
        const float* bcol = Bs + cg * 4;
        float* yout = Ys + row * 20 + cg * 4;

        // GEMM2 mapping (accumulators persist): k=t&63, rg=t>>6
        int k_own = t & 63;
        int rg    = t >> 6;
        u64 acc01 = 0ull, acc23 = 0ull;
        const float* yin = Ys + rg * 4;

        for (int tile = 0; tile < ntiles; ++tile) {
            const float* Ab = (tile & 1) ? As1 : As0;
            cp_wait<0>();
            __syncthreads();

            // ---- GEMM1 (f32x2): y[row][4cg..] = sum_d X[row][d]*B[d][4cg..] ----
            u64 y01 = 0ull, y23 = 0ull;
            #pragma unroll 8
            for (int s = 0; s < 32; ++s) {
                float4 x4 = *(const float4*)(xrow + s * 4);
                const float* bbase = bcol + (4 * s) * RD;
                ulonglong2 b0 = *(const ulonglong2*)(bbase);
                ulonglong2 b1 = *(const ulonglong2*)(bbase + RD);
                ulonglong2 b2 = *(const ulonglong2*)(bbase + 2 * RD);
                ulonglong2 b3 = *(const ulonglong2*)(bbase + 3 * RD);
                u64 xx;
                xx = pack2(x4.x); fma2(y01, xx, b0.x); fma2(y23, xx, b0.y);
                xx = pack2(x4.y); fma2(y01, xx, b1.x); fma2(y23, xx, b1.y);
                xx = pack2(x4.z); fma2(y01, xx, b2.x); fma2(y23, xx, b2.y);
                xx = pack2(x4.w); fma2(y01, xx, b3.x); fma2(y23, xx, b3.y);
            }
            {
                float2 lo = unpack2(y01), hi = unpack2(y23);
                *(float4*)yout = make_float4(lo.x, lo.y, hi.x, hi.y);
            }
            __syncthreads();              // Ys complete; X now dead

            if (tile + 1 < ntiles) {
                int lt    = l0 + (tile + 1) * TILE;
                int valid = min(TILE, nrows - (tile + 1) * TILE);
                issue_tile64(embB, Ac, Xs, (tile & 1) ? As0 : As1, lt, valid, t);
                cp_commit();
            }

            // ---- GEMM2 (f32x2): U[k][4rg..] += sum_l A[l][k]*y[l][4rg..] ----
            #pragma unroll 8
            for (int l = 0; l < TILE; ++l) {
                u64 aa = pack2(Ab[l * RL + k_own]);
                ulonglong2 y2 = *(const ulonglong2*)(yin + l * 20);
                fma2(acc01, aa, y2.x);
                fma2(acc23, aa, y2.y);
            }
        }

        float2 a01 = unpack2(acc01), a23 = unpack2(acc23);
        float* Ub = g_U + b * (RL * RD) + k_own * RD + rg * 4;
        atomicAdd(Ub + 0, a01.x);
        atomicAdd(Ub + 1, a01.y);
        atomicAdd(Ub + 2, a23.x);
        atomicAdd(Ub + 3, a23.y);
    }
}

// -------------------------------------------------------------------
// Tail GEMM (512 threads): C[64 x 512] += A[64 x Ktot] @ W[Ktot x 512]
//   MODE 0: A=g_U  (Ktot=1024, KC=128), C=g_z
//   MODE 1: A=g_z  (Ktot=512,  KC=64),  C=g_h
//   MODE 2: A=g_ha (Ktot=512,  KC=64),  C=outp, +bias on ks==0
// grid 128 = 16 nt x (Ktot/KC) ks. Thread: l=t&63 (row), wn=t>>6 (4 cols).
// -------------------------------------------------------------------
template<int KC, int MODE>
__global__ __launch_bounds__(512) void k_tgemm(
        const float* __restrict__ W, float* __restrict__ outp,
        const float* __restrict__ bias, int Ktot) {
    const float* A = (MODE == 0) ? g_U : (MODE == 1) ? g_z : g_ha;
    float*       C = (MODE == 0) ? g_z : (MODE == 1) ? g_h : outp;

    constexpr int SA = KC + 1;
    extern __shared__ float tsm[];
    float* As = tsm;                 // BB * SA
    float* Ws = tsm + BB * SA;       // KC * 32

    int nt = blockIdx.x & 15;
    int ks = blockIdx.x >> 4;
    int n0 = nt * 32;
    int kbase = ks * KC;
    int t = threadIdx.x;

    #pragma unroll
    for (int i = t; i < BB * KC; i += 512) {
        int row = i / KC, k = i % KC;       // consecutive t -> consecutive k
        As[row * SA + k] = A[(size_t)row * Ktot + kbase + k];
    }
    #pragma unroll
    for (int i = t; i < KC * 8; i += 512) {
        int row = i >> 3, seg = i & 7;
        *(float4*)&Ws[row * 32 + seg * 4] =
            *(const float4*)&W[(size_t)(kbase + row) * DOUT + n0 + seg * 4];
    }
    __syncthreads();

    int l  = t & 63;          // row; warp lanes -> consecutive l, SA odd -> conflict-free
    int wn = t >> 6;          // 0..7 (warp-uniform -> Ws broadcast)
    u64 c0 = 0ull, c1 = 0ull;
    const float* ap = As + l * SA;
    const float* wp = Ws + wn * 4;
    #pragma unroll 8
    for (int k = 0; k < KC; ++k) {
        u64 aa = pack2(ap[k]);
        ulonglong2 w2 = *(const ulonglong2*)(wp + k * 32);
        fma2(c0, aa, w2.x);
        fma2(c1, aa, w2.y);
    }
    int col = n0 + wn * 4;
    float2 r0 = unpack2(c0), r1 = unpack2(c1);
    if (MODE == 2 && ks == 0) {
        float4 bv = *(const float4*)(bias + col);
        r0.x += bv.x; r0.y += bv.y; r1.x += bv.z; r1.y += bv.w;
    }
    float* Cp = C + (size_t)l * DOUT + col;
    atomicAdd(Cp + 0, r0.x); atomicAdd(Cp + 1, r0.y);
    atomicAdd(Cp + 2, r1.x); atomicAdd(Cp + 3, r1.y);
}

// -------------------------------------------------------------------
// k5: per-row bias + LayerNorm + ReLU. grid 64, 256 threads.
// -------------------------------------------------------------------
__global__ __launch_bounds__(256) void k_ln(const float* __restrict__ b1,
                                            const float* __restrict__ lnw,
                                            const float* __restrict__ lnb) {
    int b = blockIdx.x, t = threadIdx.x;
    float v0 = g_h[b * DOUT + t]       + b1[t];
    float v1 = g_h[b * DOUT + 256 + t] + b1[256 + t];
    float s  = v0 + v1;
    float sq = v0 * v0 + v1 * v1;
    for (int o = 16; o > 0; o >>= 1) {
        s  += __shfl_down_sync(0xFFFFFFFFu, s,  o);
        sq += __shfl_down_sync(0xFFFFFFFFu, sq, o);
    }
    __shared__ float rs[8], rq[8];
    if ((t & 31) == 0) { rs[t >> 5] = s; rq[t >> 5] = sq; }
    __syncthreads();
    float tot = 0.f, totq = 0.f;
    #pragma unroll
    for (int i = 0; i < 8; ++i) { tot += rs[i]; totq += rq[i]; }
    float mu  = tot / (float)DOUT;
    float var = fmaxf(totq / (float)DOUT - mu * mu, 0.f);
    float rstd = rsqrtf(var + LN_EPS);
    float o0 = (v0 - mu) * rstd * lnw[t]       + lnb[t];
    float o1 = (v1 - mu) * rstd * lnw[256 + t] + lnb[256 + t];
    g_ha[b * DOUT + t]       = fmaxf(o0, 0.f);
    g_ha[b * DOUT + 256 + t] = fmaxf(o1, 0.f);
}

// -------------------------------------------------------------------
extern "C" void kernel_launch(void* const* d_in, const int* in_sizes, int n_in,
                              void* d_out, int out_size) {
    const float*         emb  = (const float*)d_in[0];
    const unsigned char* mask = (const unsigned char*)d_in[1];
    const float*         Bc   = (const float*)d_in[2];
    const float*         Ac   = (const float*)d_in[3];
    const float*         Hc   = (const float*)d_in[4];
    const float*         W1   = (const float*)d_in[5];
    const float*         b1   = (const float*)d_in[6];
    const float*         lnw  = (const float*)d_in[7];
    const float*         lnb  = (const float*)d_in[8];
    const float*         W2   = (const float*)d_in[9];
    const float*         b2   = (const float*)d_in[10];
    float* out = (float*)d_out;

    const int SM128 = (BB * 129 + 128 * 32) * 4;   // 49408 B
    const int SM64  = (BB * 65  + 64  * 32) * 4;   // 24832 B

    cudaFuncSetAttribute(k_stageA, cudaFuncAttributeMaxDynamicSharedMemorySize, 81920);
    cudaFuncSetAttribute(k_tgemm<128, 0>, cudaFuncAttributeMaxDynamicSharedMemorySize, SM128);
    cudaFuncSetAttribute(k_tgemm<64, 1>,  cudaFuncAttributeMaxDynamicSharedMemorySize, SM64);
    cudaFuncSetAttribute(k_tgemm<64, 2>,  cudaFuncAttributeMaxDynamicSharedMemorySize, SM64);

    k_detect<<<8, 512>>>(mask, out);
    k_stageA<<<BB * (LMAX / CHUNK), 256, 79872>>>(emb, Bc, Ac, mask);   // 512 blocks
    // z = U @ Hc   (K=1024, KC=128 -> 8 ksplits x 16 nt = 128 blocks)
    k_tgemm<128, 0><<<128, 512, SM128>>>(Hc, nullptr, nullptr, 1024);
    // h = z @ W1   (K=512, KC=64 -> 8 ksplits x 16 nt = 128 blocks)
    k_tgemm<64, 1><<<128, 512, SM64>>>(W1, nullptr, nullptr, 512);
    k_ln<<<BB, 256>>>(b1, lnw, lnb);
    // out = ha @ W2 + b2
    k_tgemm<64, 2><<<128, 512, SM64>>>(W2, out, b2, 512);
}